// round 6
// baseline (speedup 1.0000x reference)
#include <cuda_runtime.h>

// delta_layer: out[b,t,:] = [ x, delta(x), delta(delta(x)) ]
// delta(y)[t] = 0.5*(y[c(t+1)]-y[c(t-1)]) + 0.25*(y[c(t+2)]-y[c(t-2)]), c = clamp [0,T-1]
// Shapes fixed: B=32, T=4096, D=256, window=2.
//
// Round-6 layout: ONE WARP OWNS ONE FULL ROW STREAM. Lane l holds float4
// channel-groups l and l+32, so per iteration a warp reads a full 1KB input
// row (2x LDG.128 contiguous) and writes a full 3KB output row (6x STG.128
// contiguous). Per-warp DRAM streams are perfectly sequential -> maximal
// row-buffer locality. The concat layout means lane l's delta/ddelta values
// land at positions l and l+32 of each segment: no shuffles.
//
// Interior rows use the fused 9-tap double-delta:
//   dd(t) = 0.0625(x[t-4]+x[t+4]) + 0.25(x[t-3]+x[t+3]) + 0.25(x[t-2]+x[t+2])
//         - 0.25(x[t-1]+x[t+1]) - 0.625 x[t]

#define B_N 32
#define T_N 4096
#define D4_N 64            // 256 floats / 4 (float4 groups per row)
#define OD4_N 192          // 768 floats / 4
#define L_N 32             // rows per warp chunk
#define CHUNKS (T_N / L_N) // 128

__device__ __forceinline__ float4 f4_delta(float4 m2, float4 m1, float4 p1, float4 p2) {
    float4 r;
    r.x = 0.5f * p1.x - 0.5f * m1.x + 0.25f * p2.x - 0.25f * m2.x;
    r.y = 0.5f * p1.y - 0.5f * m1.y + 0.25f * p2.y - 0.25f * m2.y;
    r.z = 0.5f * p1.z - 0.5f * m1.z + 0.25f * p2.z - 0.25f * m2.z;
    r.w = 0.5f * p1.w - 0.5f * m1.w + 0.25f * p2.w - 0.25f * m2.w;
    return r;
}

__device__ __forceinline__ float dd9(float a0, float a1, float a2, float a3, float a4,
                                     float a5, float a6, float a7, float a8) {
    return 0.0625f * (a0 + a8) + 0.25f * (a1 + a7) + 0.25f * (a2 + a6)
         - 0.25f * (a3 + a5) - 0.625f * a4;
}

__device__ __forceinline__ float4 f4_dd(const float4* r) {
    float4 o;
    o.x = dd9(r[0].x, r[1].x, r[2].x, r[3].x, r[4].x, r[5].x, r[6].x, r[7].x, r[8].x);
    o.y = dd9(r[0].y, r[1].y, r[2].y, r[3].y, r[4].y, r[5].y, r[6].y, r[7].y, r[8].y);
    o.z = dd9(r[0].z, r[1].z, r[2].z, r[3].z, r[4].z, r[5].z, r[6].z, r[7].z, r[8].z);
    o.w = dd9(r[0].w, r[1].w, r[2].w, r[3].w, r[4].w, r[5].w, r[6].w, r[7].w, r[8].w);
    return o;
}

__global__ void __launch_bounds__(128, 5)
delta_layer_kernel(const float4* __restrict__ x, float4* __restrict__ out) {
    const int lane  = threadIdx.x & 31;
    const int widx  = threadIdx.x >> 5;                 // 0..3
    const int chunk = blockIdx.x * 4 + widx;            // 0..127
    const int b     = blockIdx.y;
    const int t0    = chunk * L_N;

    const int g0 = lane;        // float4 group for channels [4*lane, 4*lane+4)
    const int g1 = lane + 32;   // float4 group for channels [128+4*lane, ...)

    const float4* __restrict__ xb = x   + (size_t)b * T_N * D4_N;
    float4*       __restrict__ ob = out + (size_t)b * T_N * OD4_N;

    if (chunk != 0 && chunk != CHUNKS - 1) {
        // ---- interior fast path: two 9-deep float4 rings (groups g0, g1) ----
        float4 a[9], c[9];
#pragma unroll
        for (int j = 0; j < 9; ++j) {
            a[j] = __ldg(xb + (size_t)(t0 - 4 + j) * D4_N + g0);
            c[j] = __ldg(xb + (size_t)(t0 - 4 + j) * D4_N + g1);
        }

#pragma unroll 4
        for (int i = 0; i < L_N; ++i) {
            const int t = t0 + i;
            // prefetch next row (both halves) before the arithmetic
            // max index: t0+31+5 <= 4068 < T for interior chunks
            float4 n0 = __ldg(xb + (size_t)(t + 5) * D4_N + g0);
            float4 n1 = __ldg(xb + (size_t)(t + 5) * D4_N + g1);

            float4* orow = ob + (size_t)t * OD4_N;
            // segment 0: x (full 1KB, contiguous across the warp's 2 stores)
            __stcs(orow + g0, a[4]);
            __stcs(orow + g1, c[4]);
            // segment 1: delta
            __stcs(orow + D4_N + g0, f4_delta(a[2], a[3], a[5], a[6]));
            __stcs(orow + D4_N + g1, f4_delta(c[2], c[3], c[5], c[6]));
            // segment 2: double delta
            __stcs(orow + 2 * D4_N + g0, f4_dd(a));
            __stcs(orow + 2 * D4_N + g1, f4_dd(c));

#pragma unroll
            for (int j = 0; j < 8; ++j) { a[j] = a[j + 1]; c[j] = c[j + 1]; }
            a[8] = n0; c[8] = n1;
        }
    } else {
        // ---- edge path: generic clamped math (2 of 128 chunks per b) ----
        auto LD = [&](int t, int g) -> float4 {
            t = t < 0 ? 0 : (t > T_N - 1 ? T_N - 1 : t);
            return __ldg(xb + (size_t)t * D4_N + g);
        };
        auto DELTA_AT = [&](int s, int g) -> float4 {
            s = s < 0 ? 0 : (s > T_N - 1 ? T_N - 1 : s);
            return f4_delta(LD(s - 2, g), LD(s - 1, g), LD(s + 1, g), LD(s + 2, g));
        };

        for (int i = 0; i < L_N; ++i) {
            const int t = t0 + i;
            float4* orow = ob + (size_t)t * OD4_N;
#pragma unroll
            for (int h = 0; h < 2; ++h) {
                const int g = h ? g1 : g0;
                orow[g]            = LD(t, g);
                orow[D4_N + g]     = DELTA_AT(t, g);
                orow[2 * D4_N + g] = f4_delta(DELTA_AT(t - 2, g), DELTA_AT(t - 1, g),
                                              DELTA_AT(t + 1, g), DELTA_AT(t + 2, g));
            }
        }
    }
}

extern "C" void kernel_launch(void* const* d_in, const int* in_sizes, int n_in,
                              void* d_out, int out_size) {
    const float4* x = (const float4*)d_in[0];
    float4* out     = (float4*)d_out;
    // d_in[1] = window (always 2) — baked in.

    dim3 block(128, 1);            // 4 warps = 4 chunks
    dim3 grid(CHUNKS / 4, B_N);    // (32, 32) = 1024 blocks
    delta_layer_kernel<<<grid, block>>>(x, out);
}

// round 7
// speedup vs baseline: 1.2914x; 1.2914x over previous
#include <cuda_runtime.h>
#include <cstdint>

// delta_layer: out[b,t,:] = [ x, delta(x), delta(delta(x)) ]
// delta(y)[t] = 0.5*(y[c(t+1)]-y[c(t-1)]) + 0.25*(y[c(t+2)]-y[c(t-2)]), c = clamp [0,T-1]
// Shapes fixed: B=32, T=4096, D=256, window=2.
//
// Round-7: direction-batched bulk memory. Each block:
//   1) ONE cp.async.bulk load  (16 KB: rows t0-4 .. t0+11, contiguous)
//   2) compute 8 rows in registers (9-deep float2 ring fed from smem)
//   3) ONE cp.async.bulk store (24 KB: 8 output rows x 3KB, contiguous)
// Long same-direction DRAM bursts instead of interleaved 32B sectors.
// Interior rows use the fused 9-tap double-delta:
//   dd(t) = 0.0625(x[t-4]+x[t+4]) + 0.25(x[t-3]+x[t+3]) + 0.25(x[t-2]+x[t+2])
//         - 0.25(x[t-1]+x[t+1]) - 0.625 x[t]

#define B_N 32
#define T_N 4096
#define F2_N 128            // float2 per input row (256 floats)
#define OF2_N 384           // float2 per output row (768 floats)
#define L_N 8               // rows per tile
#define CHUNKS (T_N / L_N)  // 512
#define IN_ROWS (L_N + 8)   // 16
#define IN_BYTES (IN_ROWS * F2_N * 8)   // 16384
#define OUT_BYTES (L_N * OF2_N * 8)     // 24576

__device__ __forceinline__ uint32_t smem_u32(const void* p) {
    uint32_t a;
    asm("{ .reg .u64 t; cvta.to.shared.u64 t, %1; cvt.u32.u64 %0, t; }"
        : "=r"(a) : "l"(p));
    return a;
}

__device__ __forceinline__ float2 f2_delta(float2 m2, float2 m1, float2 p1, float2 p2) {
    float2 r;
    r.x = 0.5f * (p1.x - m1.x) + 0.25f * (p2.x - m2.x);
    r.y = 0.5f * (p1.y - m1.y) + 0.25f * (p2.y - m2.y);
    return r;
}

__device__ __forceinline__ float dd9(float a0, float a1, float a2, float a3, float a4,
                                     float a5, float a6, float a7, float a8) {
    return 0.0625f * (a0 + a8) + 0.25f * (a1 + a7) + 0.25f * (a2 + a6)
         - 0.25f * (a3 + a5) - 0.625f * a4;
}

struct SmemLayout {
    alignas(128) unsigned long long mbar;
    alignas(128) float2 in[IN_ROWS * F2_N];   // 16 KB
    alignas(128) float2 outt[L_N * OF2_N];    // 24 KB
};

__global__ void __launch_bounds__(128, 5)
delta_layer_kernel(const float2* __restrict__ x, float2* __restrict__ out) {
    __shared__ SmemLayout s;

    const int tid   = threadIdx.x;          // 0..127 = float2 channel group
    const int chunk = blockIdx.x;            // 0..511
    const int b     = blockIdx.y;
    const int t0    = chunk * L_N;

    if (chunk != 0 && chunk != CHUNKS - 1) {
        // ---------------- interior: bulk load -> ring compute -> bulk store ----
        const uint32_t mbar  = smem_u32(&s.mbar);
        const uint32_t s_in  = smem_u32(s.in);
        const uint32_t s_out = smem_u32(s.outt);

        if (tid == 0) {
            asm volatile("mbarrier.init.shared.b64 [%0], 1;" :: "r"(mbar) : "memory");
        }
        __syncthreads();
        if (tid == 0) {
            asm volatile("mbarrier.arrive.expect_tx.shared.b64 _, [%0], %1;"
                         :: "r"(mbar), "r"((uint32_t)IN_BYTES) : "memory");
            const float2* src = x + ((size_t)b * T_N + (t0 - 4)) * F2_N;
            asm volatile(
                "cp.async.bulk.shared::cluster.global.mbarrier::complete_tx::bytes "
                "[%0], [%1], %2, [%3];"
                :: "r"(s_in), "l"(src), "r"((uint32_t)IN_BYTES), "r"(mbar) : "memory");
        }
        // wait for the bulk load (phase 0)
        asm volatile(
            "{\n\t.reg .pred P;\n\t"
            "W%=: mbarrier.try_wait.parity.shared::cta.b64 P, [%0], 0;\n\t"
            "@!P bra W%=;\n\t}"
            :: "r"(mbar) : "memory");

        // ring over smem rows: smem row s = global row t0-4+s
        const float2* inp = s.in + tid;
        float2 r[9];
#pragma unroll
        for (int j = 0; j < 9; ++j) r[j] = inp[j * F2_N];

#pragma unroll
        for (int i = 0; i < L_N; ++i) {
            float2* orow = s.outt + i * OF2_N + tid;
            orow[0]        = r[4];                          // x
            orow[F2_N]     = f2_delta(r[2], r[3], r[5], r[6]); // delta
            float2 dd;
            dd.x = dd9(r[0].x, r[1].x, r[2].x, r[3].x, r[4].x, r[5].x, r[6].x, r[7].x, r[8].x);
            dd.y = dd9(r[0].y, r[1].y, r[2].y, r[3].y, r[4].y, r[5].y, r[6].y, r[7].y, r[8].y);
            orow[2 * F2_N] = dd;                            // double delta

            if (i < L_N - 1) {
#pragma unroll
                for (int j = 0; j < 8; ++j) r[j] = r[j + 1];
                r[8] = inp[(i + 9) * F2_N];
            }
        }
        __syncthreads();

        if (tid == 0) {
            asm volatile("fence.proxy.async.shared::cta;" ::: "memory");
            float2* dst = out + ((size_t)b * T_N + t0) * OF2_N;
            asm volatile(
                "cp.async.bulk.global.shared::cta.bulk_group [%0], [%1], %2;"
                :: "l"(dst), "r"(s_out), "r"((uint32_t)OUT_BYTES) : "memory");
            asm volatile("cp.async.bulk.commit_group;" ::: "memory");
            asm volatile("cp.async.bulk.wait_group 0;" ::: "memory");
        }
    } else {
        // ---------------- edge path: generic clamped math, direct global ------
        const float2* __restrict__ xb = x   + (size_t)b * T_N * F2_N  + tid;
        float2*       __restrict__ ob = out + (size_t)b * T_N * OF2_N + tid;

        auto LD = [&](int t) -> float2 {
            t = t < 0 ? 0 : (t > T_N - 1 ? T_N - 1 : t);
            return __ldg(xb + (size_t)t * F2_N);
        };
        auto DELTA_AT = [&](int sdx) -> float2 {
            sdx = sdx < 0 ? 0 : (sdx > T_N - 1 ? T_N - 1 : sdx);
            return f2_delta(LD(sdx - 2), LD(sdx - 1), LD(sdx + 1), LD(sdx + 2));
        };

        for (int i = 0; i < L_N; ++i) {
            const int t = t0 + i;
            const size_t orow = (size_t)t * OF2_N;
            ob[orow]           = LD(t);
            ob[orow + F2_N]    = DELTA_AT(t);
            ob[orow + 2*F2_N]  =
                f2_delta(DELTA_AT(t - 2), DELTA_AT(t - 1), DELTA_AT(t + 1), DELTA_AT(t + 2));
        }
    }
}

extern "C" void kernel_launch(void* const* d_in, const int* in_sizes, int n_in,
                              void* d_out, int out_size) {
    const float2* x = (const float2*)d_in[0];
    float2* out     = (float2*)d_out;
    // d_in[1] = window (always 2) — baked in.

    dim3 block(128, 1);
    dim3 grid(CHUNKS, B_N);   // (512, 32) = 16384 blocks
    delta_layer_kernel<<<grid, block>>>(x, out);
}